// round 14
// baseline (speedup 1.0000x reference)
#include <cuda_runtime.h>
#include <math.h>

#define BN   64
#define PAST 128
#define FUT  64
#define NF   51
#define NO   50
#define NH   4
#define N1   (BN*PAST)   /* 8192 */
#define N2   (BN*FUT)    /* 4096 */
#define E1N  (N1*16)
#define E2N  (N2*16)
#define T1   (E1N+N1)    /* 139264 */
#define T2   (E2N+N2)    /* 69632 */
#define G1B  (N1/16)     /* 512 gemm blocks */
#define X2B  (N2/16)     /* 256 x2-pre blocks */
#define MB   4
#define AGRID (G1B + X2B + MB + 1)
#define BGRID 296
#define DGRID 512
#define Z2PB 20
#define Z2B  ((N2+Z2PB-1)/Z2PB)  /* 205 */
#define P0TOT (Z2B + N1)         /* phase-0 vblocks: z2 first, then agg1 */

// ---------------- scratch ----------------
__device__ float d_y  [N1];
__device__ float d_x2 [N2*NO];
__device__ float d_h1 [N1*NH*NO];
__device__ __align__(16) float d_as1[N1*NH];
__device__ __align__(16) float d_ad1[N1*NH];
__device__ float d_x1o[N1*NO];
__device__ float d_M  [NO*NO];
__device__ float d_q1h[N1];
__device__ float d_z2 [N2*NO];
__device__ __align__(16) float d_h2 [N2*NH];
__device__ __align__(16) float d_as2[N2*NH];
__device__ __align__(16) float d_ad2[N2*NH];
__device__ unsigned d_maskw[FUT*4];
__device__ int   d_cnt1[N1];     // zero at load; scan re-zeroes per call
__device__ int   d_off1[N1+1];
__device__ int   d_cur1[N1];
__device__ int   d_csr1[T1];
__device__ int   d_cnt2[N2];
__device__ int   d_off2[N2+1];
__device__ int   d_cur2[N2];
__device__ int   d_csr2[T2];

// grid barrier (monotonic flag: replay-safe). kB and kD never run concurrently.
__device__ unsigned g_barcnt = 0;
__device__ unsigned g_barflag = 0;

__device__ __forceinline__ void grid_barrier() {
    __syncthreads();
    if (threadIdx.x == 0) {
        unsigned old = *((volatile unsigned*)&g_barflag);
        __threadfence();
        unsigned a = atomicAdd(&g_barcnt, 1u);
        if (a == gridDim.x - 1) {
            atomicExch(&g_barcnt, 0u);
            __threadfence();
            atomicExch(&g_barflag, old + 1u);
        } else {
            while (*((volatile unsigned*)&g_barflag) == old) __nanosleep(64);
        }
        __threadfence();
    }
    __syncthreads();
}

__device__ __forceinline__ float warp_sum(float v) {
    #pragma unroll
    for (int o = 16; o; o >>= 1) v += __shfl_xor_sync(0xffffffffu, v, o);
    return v;
}
__device__ __forceinline__ float lrelu(float x) { return x > 0.f ? x : 0.2f * x; }

// ================= A: gemm | x2 pre | M | mask (all independent) =================
__global__ void kA(const int* __restrict__ cat1, const float* __restrict__ num1,
                   const int* __restrict__ cat2, const float* __restrict__ num2,
                   const int* __restrict__ A,
                   const float* __restrict__ e0w, const float* __restrict__ e1w,
                   const float* __restrict__ e2w,
                   const float* __restrict__ lin, const float* __restrict__ asrc,
                   const float* __restrict__ adst, const float* __restrict__ W) {
    int bb = blockIdx.x, t = threadIdx.x;
    if (bb < G1B) {
        __shared__ float xs[16*NF];
        __shared__ float hs[16*NH*NO];
        int n0 = bb*16;
        for (int idx = t; idx < 16*NF; idx += 256) {
            int j = idx / NF, k = idx % NF, n = n0 + j;
            float v;
            if      (k < 16) v = e0w[cat1[n*3+0]*16 + k];
            else if (k < 24) v = e1w[cat1[n*3+1]*8  + (k-16)];
            else if (k < 48) v = e2w[cat1[n*3+2]*24 + (k-24)];
            else             v = num1[n*3 + (k-48)];
            xs[idx] = v;
            if (k == NF-1) d_y[n] = v;
        }
        __syncthreads();
        if (t < NH*NO) {
            float acc[16];
            #pragma unroll
            for (int j = 0; j < 16; j++) acc[j] = 0.f;
            for (int k = 0; k < NF; k++) {
                float l = __ldg(&lin[k*(NH*NO) + t]);
                #pragma unroll
                for (int j = 0; j < 16; j++) acc[j] += xs[j*NF + k] * l;
            }
            #pragma unroll
            for (int j = 0; j < 16; j++) {
                d_h1[(n0+j)*(NH*NO) + t] = acc[j];
                hs[j*(NH*NO) + t] = acc[j];
            }
        }
        __syncthreads();
        if (t < 128) {
            int j = t >> 3, r = t & 7, head = r & 3;
            const float* att = (r < 4) ? asrc : adst;
            float a = 0.f;
            #pragma unroll
            for (int c = 0; c < NO; c++)
                a += hs[j*(NH*NO) + head*NO + c] * att[head*NO + c];
            if (r < 4) d_as1[(n0+j)*NH + head] = a;
            else       d_ad1[(n0+j)*NH + head] = a;
        }
        return;
    }
    bb -= G1B;
    if (bb < X2B) {
        int base = bb*16;
        for (int idx = t; idx < 16*NO; idx += 256) {
            int ln = idx / NO, c = idx % NO;
            int n = base + ln;
            float v;
            if      (c < 16) v = e0w[cat2[n*3+0]*16 + c];
            else if (c < 24) v = e1w[cat2[n*3+1]*8  + (c-16)];
            else if (c < 48) v = e2w[cat2[n*3+2]*24 + (c-24)];
            else             v = num2[n*3 + (c-48)];
            d_x2[n*NO + c] = v;
        }
        return;
    }
    bb -= X2B;
    if (bb < MB) {
        int lo = bb*625, hi = lo + 625;
        for (int idx = lo + t; idx < hi; idx += 256) {
            int i = idx / NO, j = idx % NO;
            float s = 0.f;
            #pragma unroll
            for (int k = 0; k < 64; k++) s += __ldg(&W[i*64+k]) * __ldg(&W[j*64+k]);
            d_M[idx] = 2.f * s;
        }
        return;
    }
    {
        int f = t >> 2, wd = t & 3;
        unsigned u = 0;
        for (int i = 0; i < 32; i++)
            if (A[(wd*32+i)*(PAST+FUT) + PAST + f]) u |= (1u << i);
        d_maskw[f*4 + wd] = u;
    }
}

// ============ B: hist -> barrier -> scan -> barrier -> scatter (input-only) ============
__device__ void scan2(int* cnt, int* off, int* cur, int NN) {
    __shared__ int wt[8];
    int t = threadIdx.x, lane = t & 31, wid = t >> 5;
    int chunk = NN >> 8;
    int start = t * chunk;
    int s = 0;
    for (int i = 0; i < chunk; i++) s += cnt[start+i] + 1;   // + self loop
    int v = s;
    #pragma unroll
    for (int o = 1; o < 32; o <<= 1) {
        int u = __shfl_up_sync(0xffffffffu, v, o);
        if (lane >= o) v += u;
    }
    if (lane == 31) wt[wid] = v;
    __syncthreads();
    if (t == 0) {
        int r = 0;
        #pragma unroll
        for (int i = 0; i < 8; i++) { int x = wt[i]; wt[i] = r + x; r += x; }
    }
    __syncthreads();
    int run = v - s + (wid ? wt[wid-1] : 0);
    for (int i = 0; i < chunk; i++) {
        int c = cnt[start+i];
        cnt[start+i] = 0;
        off[start+i] = run;
        cur[start+i] = run;
        run += c + 1;
    }
    if (t == 255) off[NN] = run;
}

__global__ void kB(const int* __restrict__ e1, const int* __restrict__ e2) {
    int t = threadIdx.x;
    for (int i = blockIdx.x*256 + t; i < E1N + E2N; i += BGRID*256) {
        if (i < E1N) atomicAdd(&d_cnt1[e1[E1N + i]], 1);
        else         atomicAdd(&d_cnt2[e2[E2N + (i - E1N)]], 1);
    }
    grid_barrier();
    if (blockIdx.x == 0) scan2(d_cnt1, d_off1, d_cur1, N1);
    else if (blockIdx.x == 1) scan2(d_cnt2, d_off2, d_cur2, N2);
    grid_barrier();
    for (int i = blockIdx.x*256 + t; i < T1 + T2; i += BGRID*256) {
        if (i < T1) {
            int s, d;
            if (i < E1N) { s = e1[i]; d = e1[E1N + i]; }
            else         { s = d = i - E1N; }
            d_csr1[atomicAdd(&d_cur1[d], 1)] = s;
        } else {
            int j = i - T1;
            int s, d;
            if (j < E2N) { s = e2[j]; d = e2[E2N + j]; }
            else         { s = d = j - E2N; }
            d_csr2[atomicAdd(&d_cur2[d], 1)] = s;
        }
    }
}

// ==== D: [z2|agg1 vblocks] -> barrier -> attn -> barrier -> agg2 (one kernel) ====
#define SMEMF 7700
__global__ void __launch_bounds__(256, 4) kD(
        const float* __restrict__ bias1,
        const float* __restrict__ lin,
        const float* __restrict__ asrc, const float* __restrict__ adst,
        const float* __restrict__ bias2, float* __restrict__ out) {
    int t = threadIdx.x;
    __shared__ float sbuf[SMEMF];   // 30800 B, unioned across phases

    // ---------------- phase 0: z2 (vb < Z2B) | agg1 (vb >= Z2B) ----------------
    for (int vb = blockIdx.x; vb < P0TOT; vb += DGRID) {
        if (vb < Z2B) {
            int base = vb * Z2PB;
            float* Ms  = sbuf;              // 2500
            float* x2s = sbuf + NO*NO;      // 1000
            for (int idx = t; idx < NO*NO; idx += 256) Ms[idx] = d_M[idx];
            for (int idx = t; idx < Z2PB*NO; idx += 256) {
                int gl = base*NO + idx;
                x2s[idx] = (gl < N2*NO) ? d_x2[gl] : 0.f;
            }
            __syncthreads();
            for (int idx = t; idx < Z2PB*NO; idx += 256) {
                int ln = idx / NO, c = idx % NO;
                int node = base + ln;
                if (node < N2) {
                    float z = 0.f;
                    #pragma unroll
                    for (int j = 0; j < NO; j++) z += Ms[c*NO + j] * x2s[ln*NO + j];
                    d_z2[node*NO + c] = z;
                }
            }
            __syncthreads();
            continue;
        }
        int n = vb - Z2B;
        int wp = t >> 5;
        int w  = wp >> 1;
        int eh = wp & 1;
        int lane = t & 31;
        int beg = d_off1[n], end = d_off1[n+1];
        float ad = d_ad1[n*NH + w];

        float* so      = sbuf;          // 50
        float* ssum_sh = sbuf + 64;     // 4
        float* red     = sbuf + 96;     // 256
        if (t < NO) so[t] = 0.f;
        if (t < NH) ssum_sh[t] = 0.f;
        __syncthreads();

        float ssum = 0.f, a0 = 0.f, a1 = 0.f, b0 = 0.f, b1 = 0.f;
        int c0 = lane, c1 = lane + 32;
        bool has1 = (c1 < NO);
        int i = beg + eh;
        for (; i + 2 < end; i += 4) {
            int s0 = d_csr1[i], s1 = d_csr1[i+2];
            float w0 = __expf(lrelu(__ldg(&d_as1[s0*NH + w]) + ad));
            float w1 = __expf(lrelu(__ldg(&d_as1[s1*NH + w]) + ad));
            ssum += w0 + w1;
            const float* h0 = &d_h1[s0*(NH*NO) + w*NO];
            const float* h1 = &d_h1[s1*(NH*NO) + w*NO];
            a0 += w0 * h0[c0];
            b0 += w1 * h1[c0];
            if (has1) { a1 += w0 * h0[c1]; b1 += w1 * h1[c1]; }
        }
        if (i < end) {
            int s0 = d_csr1[i];
            float w0 = __expf(lrelu(__ldg(&d_as1[s0*NH + w]) + ad));
            ssum += w0;
            const float* h0 = &d_h1[s0*(NH*NO) + w*NO];
            a0 += w0 * h0[c0];
            if (has1) a1 += w0 * h0[c1];
        }
        a0 += b0; a1 += b1;
        if (lane == 0) atomicAdd(&ssum_sh[w], ssum);
        __syncthreads();
        float inv = 0.25f / (ssum_sh[w] + 1e-16f);
        atomicAdd(&so[c0], a0 * inv);
        if (has1) atomicAdd(&so[c1], a1 * inv);
        __syncthreads();
        if (t < NO) {
            float v = so[t] + bias1[t];
            so[t] = v;
            d_x1o[n*NO + t] = v;
        }
        __syncthreads();
        float p = 0.f;
        for (int r = wp; r < NO; r += 8) {
            float xr = so[r];
            float acc = __ldg(&d_M[r*NO + c0]) * so[c0];
            if (has1) acc += __ldg(&d_M[r*NO + c1]) * so[c1];
            p += acc * xr;
        }
        red[t] = p;
        __syncthreads();
        if (t < 128) red[t] += red[t+128];
        __syncthreads();
        if (t < 64) red[t] += red[t+64];
        __syncthreads();
        if (t < 32) {
            float v = red[t] + red[t+32];
            v = warp_sum(v);
            if (t == 0) d_q1h[n] = -0.5f * v;
        }
        __syncthreads();
    }
    grid_barrier();

    // ---------------- phase 1: attention + GAT2 linear (1:1 with grid) ----------------
    {
        float*    xt   = sbuf;                       // 6528
        float*    x2s  = sbuf + 6528;                // 400
        float*    zs   = sbuf + 6928;                // 400
        float*    qh   = sbuf + 7328;                // 128
        float*    yv   = sbuf + 7456;                // 128
        float*    stmp = sbuf + 7584;                // 8
        unsigned* msk  = (unsigned*)(sbuf + 7592);   // 32

        int vb = blockIdx.x;
        int b = vb >> 3, q = vb & 7;
        int fbase = q * 8;

        const float* x1src = d_x1o + (size_t)b*PAST*NO;
        for (int idx = t; idx < PAST*NO; idx += 256) {
            int p = idx / NO, c = idx % NO;
            xt[p*51 + c] = x1src[idx];
        }
        for (int idx = t; idx < 8*NO; idx += 256) {
            int fl = idx / NO, c = idx % NO;
            int nn = (b*FUT + fbase + fl)*NO + c;
            x2s[idx] = d_x2[nn];
            zs[idx]  = d_z2[nn];
        }
        if (t < PAST) { qh[t] = d_q1h[b*PAST + t]; yv[t] = d_y[b*PAST + t]; }
        if (t < 32)   msk[t] = d_maskw[(fbase + (t>>2))*4 + (t&3)];
        __syncthreads();

        int fl = t >> 5;          // warp per f
        int psub = t & 31;
        const float* zrow = zs + fl*NO;
        float sex = 0.f, swv = 0.f;
        #pragma unroll
        for (int k = 0; k < 4; k++) {
            int p = psub + k*32;
            const float* xr = xt + p*51;
            float d0 = 0.f, d1 = 0.f;
            #pragma unroll
            for (int c = 0; c < 25; c++) {
                d0 += zrow[c]      * xr[c];
                d1 += zrow[c + 25] * xr[c + 25];
            }
            float logit = qh[p] + d0 + d1;
            unsigned bit = (msk[fl*4 + k] >> psub) & 1u;
            float ex = bit ? __expf(logit) : 0.f;
            sex += ex;
            swv += ex * yv[p];
        }
        sex = warp_sum(sex);
        swv = warp_sum(swv);
        if (psub == 0) stmp[fl] = swv / (sex + 1e-16f);
        __syncthreads();

        if (t < 32) {
            int fl2 = t >> 2, h = t & 3;
            const float* xr = x2s + fl2*NO;
            float acc = 0.f;
            #pragma unroll 10
            for (int k = 0; k < NO; k++) acc += xr[k] * __ldg(&lin[k*NH + h]);
            int n = b*FUT + fbase + fl2;
            float v = acc + stmp[fl2] * __ldg(&lin[NO*NH + h]);
            d_h2[n*NH + h]  = v;
            d_as2[n*NH + h] = v * asrc[h];
            d_ad2[n*NH + h] = v * adst[h];
        }
    }
    grid_barrier();

    // ---------------- phase 2: GAT2 aggregate (8 nodes per block, 1:1) ----------------
    {
        int n = blockIdx.x*8 + (t >> 5);
        int lane = t & 31;
        int beg = d_off2[n], end = d_off2[n+1];
        float4 adv = *(const float4*)&d_ad2[n*NH];
        float ss0=0,ss1=0,ss2=0,ss3=0, ws0=0,ws1=0,ws2=0,ws3=0;
        for (int i = beg + lane; i < end; i += 32) {
            int s = d_csr2[i];
            float4 av = *(const float4*)&d_as2[s*NH];
            float4 hv = *(const float4*)&d_h2[s*NH];
            float e0 = __expf(lrelu(av.x + adv.x));
            float e1 = __expf(lrelu(av.y + adv.y));
            float e2 = __expf(lrelu(av.z + adv.z));
            float e3 = __expf(lrelu(av.w + adv.w));
            ss0+=e0; ws0+=e0*hv.x;
            ss1+=e1; ws1+=e1*hv.y;
            ss2+=e2; ws2+=e2*hv.z;
            ss3+=e3; ws3+=e3*hv.w;
        }
        ss0=warp_sum(ss0); ws0=warp_sum(ws0);
        ss1=warp_sum(ss1); ws1=warp_sum(ws1);
        ss2=warp_sum(ss2); ws2=warp_sum(ws2);
        ss3=warp_sum(ss3); ws3=warp_sum(ws3);
        if (lane == 0) {
            float total = 0.25f*ws0/(ss0+1e-16f) + 0.25f*ws1/(ss1+1e-16f)
                        + 0.25f*ws2/(ss2+1e-16f) + 0.25f*ws3/(ss3+1e-16f);
            out[n] = total + bias2[0];
        }
    }
}

// ================= launch: 3 kernels, 2-deep critical chain =================
extern "C" void kernel_launch(void* const* d_in, const int* in_sizes, int n_in,
                              void* d_out, int out_size) {
    const int*   cat1   = (const int*)  d_in[0];
    const float* num1   = (const float*)d_in[1];
    const int*   cat2   = (const int*)  d_in[2];
    const float* num2   = (const float*)d_in[3];
    const int*   e1     = (const int*)  d_in[4];
    const int*   e2     = (const int*)  d_in[5];
    const int*   A      = (const int*)  d_in[6];
    const float* emb0   = (const float*)d_in[7];
    const float* emb1   = (const float*)d_in[8];
    const float* emb2   = (const float*)d_in[9];
    const float* g1_lin = (const float*)d_in[10];
    const float* g1_as  = (const float*)d_in[11];
    const float* g1_ad  = (const float*)d_in[12];
    const float* g1_b   = (const float*)d_in[13];
    const float* g2_lin = (const float*)d_in[14];
    const float* g2_as  = (const float*)d_in[15];
    const float* g2_ad  = (const float*)d_in[16];
    const float* g2_b   = (const float*)d_in[17];
    const float* W      = (const float*)d_in[18];
    float* out = (float*)d_out;

    static cudaStream_t s1 = nullptr;
    static cudaEvent_t evF = nullptr, evB = nullptr;
    if (!s1) {
        cudaStreamCreateWithFlags(&s1, cudaStreamNonBlocking);
        cudaEventCreateWithFlags(&evF, cudaEventDisableTiming);
        cudaEventCreateWithFlags(&evB, cudaEventDisableTiming);
    }

    cudaEventRecord(evF, 0);
    cudaStreamWaitEvent(s1, evF, 0);

    // side: graph structure (input-only, parallel with kA)
    kB<<<BGRID, 256, 0, s1>>>(e1, e2);
    cudaEventRecord(evB, s1);

    // main chain: A -> D
    kA<<<AGRID, 256>>>(cat1, num1, cat2, num2, A, emb0, emb1, emb2,
                       g1_lin, g1_as, g1_ad, W);
    cudaStreamWaitEvent(0, evB, 0);
    kD<<<DGRID, 256>>>(g1_b, g2_lin, g2_as, g2_ad, g2_b, out);
}

// round 15
// speedup vs baseline: 1.6060x; 1.6060x over previous
#include <cuda_runtime.h>
#include <math.h>

#define BN   64
#define PAST 128
#define FUT  64
#define NF   51
#define NO   50
#define NH   4
#define N1   (BN*PAST)   /* 8192 */
#define N2   (BN*FUT)    /* 4096 */
#define E1N  (N1*16)
#define E2N  (N2*16)
#define T1   (E1N+N1)    /* 139264 */
#define T2   (E2N+N2)    /* 69632 */
#define PAD  64          /* bucket slots per node (max degree ~34) */
#define G1B  (N1/16)     /* 512 gemm blocks */
#define X2B  (N2/16)     /* 256 x2-pre blocks */
#define MB   4
#define AGRID (G1B + X2B + MB + 1)
#define SCB  ((T1+T2+255)/256)   /* 816 scatter blocks */
#define DGRID 512
#define Z2PB 20
#define Z2B  ((N2+Z2PB-1)/Z2PB)  /* 205 */

// ---------------- scratch ----------------
__device__ float d_y  [N1];
__device__ float d_x2 [N2*NO];
__device__ float d_h1 [N1*NH*NO];
__device__ __align__(16) float d_as1[N1*NH];
__device__ __align__(16) float d_ad1[N1*NH];
__device__ float d_x1o[N1*NO];
__device__ float d_M  [NO*NO];
__device__ float d_q1h[N1];
__device__ float d_z2 [N2*NO];
__device__ __align__(16) float d_h2 [N2*NH];
__device__ __align__(16) float d_as2[N2*NH];
__device__ __align__(16) float d_ad2[N2*NH];
__device__ unsigned d_maskw[FUT*4];
__device__ int d_cur1[N1];           // zero at load; consumer restores per call
__device__ int d_csr1[N1*PAD];       // padded buckets
__device__ int d_cur2[N2];
__device__ int d_csr2[N2*PAD];

// grid barrier (monotonic flag: replay-safe). Used only by kD.
__device__ unsigned g_barcnt = 0;
__device__ unsigned g_barflag = 0;

__device__ __forceinline__ void grid_barrier() {
    __syncthreads();
    if (threadIdx.x == 0) {
        unsigned old = *((volatile unsigned*)&g_barflag);
        __threadfence();
        unsigned a = atomicAdd(&g_barcnt, 1u);
        if (a == gridDim.x - 1) {
            atomicExch(&g_barcnt, 0u);
            __threadfence();
            atomicExch(&g_barflag, old + 1u);
        } else {
            while (*((volatile unsigned*)&g_barflag) == old) __nanosleep(64);
        }
        __threadfence();
    }
    __syncthreads();
}

__device__ __forceinline__ float warp_sum(float v) {
    #pragma unroll
    for (int o = 16; o; o >>= 1) v += __shfl_xor_sync(0xffffffffu, v, o);
    return v;
}
__device__ __forceinline__ float lrelu(float x) { return x > 0.f ? x : 0.2f * x; }

// ================= A: gemm | x2 pre | M | mask (all independent) =================
__global__ void kA(const int* __restrict__ cat1, const float* __restrict__ num1,
                   const int* __restrict__ cat2, const float* __restrict__ num2,
                   const int* __restrict__ A,
                   const float* __restrict__ e0w, const float* __restrict__ e1w,
                   const float* __restrict__ e2w,
                   const float* __restrict__ lin, const float* __restrict__ asrc,
                   const float* __restrict__ adst, const float* __restrict__ W) {
    int bb = blockIdx.x, t = threadIdx.x;
    if (bb < G1B) {
        __shared__ float xs[16*NF];
        __shared__ float hs[16*NH*NO];
        int n0 = bb*16;
        for (int idx = t; idx < 16*NF; idx += 256) {
            int j = idx / NF, k = idx % NF, n = n0 + j;
            float v;
            if      (k < 16) v = e0w[cat1[n*3+0]*16 + k];
            else if (k < 24) v = e1w[cat1[n*3+1]*8  + (k-16)];
            else if (k < 48) v = e2w[cat1[n*3+2]*24 + (k-24)];
            else             v = num1[n*3 + (k-48)];
            xs[idx] = v;
            if (k == NF-1) d_y[n] = v;
        }
        __syncthreads();
        if (t < NH*NO) {
            float acc[16];
            #pragma unroll
            for (int j = 0; j < 16; j++) acc[j] = 0.f;
            for (int k = 0; k < NF; k++) {
                float l = __ldg(&lin[k*(NH*NO) + t]);
                #pragma unroll
                for (int j = 0; j < 16; j++) acc[j] += xs[j*NF + k] * l;
            }
            #pragma unroll
            for (int j = 0; j < 16; j++) {
                d_h1[(n0+j)*(NH*NO) + t] = acc[j];
                hs[j*(NH*NO) + t] = acc[j];
            }
        }
        __syncthreads();
        if (t < 128) {
            int j = t >> 3, r = t & 7, head = r & 3;
            const float* att = (r < 4) ? asrc : adst;
            float a = 0.f;
            #pragma unroll
            for (int c = 0; c < NO; c++)
                a += hs[j*(NH*NO) + head*NO + c] * att[head*NO + c];
            if (r < 4) d_as1[(n0+j)*NH + head] = a;
            else       d_ad1[(n0+j)*NH + head] = a;
        }
        return;
    }
    bb -= G1B;
    if (bb < X2B) {
        int base = bb*16;
        for (int idx = t; idx < 16*NO; idx += 256) {
            int ln = idx / NO, c = idx % NO;
            int n = base + ln;
            float v;
            if      (c < 16) v = e0w[cat2[n*3+0]*16 + c];
            else if (c < 24) v = e1w[cat2[n*3+1]*8  + (c-16)];
            else if (c < 48) v = e2w[cat2[n*3+2]*24 + (c-24)];
            else             v = num2[n*3 + (c-48)];
            d_x2[n*NO + c] = v;
        }
        return;
    }
    bb -= X2B;
    if (bb < MB) {
        int lo = bb*625, hi = lo + 625;
        for (int idx = lo + t; idx < hi; idx += 256) {
            int i = idx / NO, j = idx % NO;
            float s = 0.f;
            #pragma unroll
            for (int k = 0; k < 64; k++) s += __ldg(&W[i*64+k]) * __ldg(&W[j*64+k]);
            d_M[idx] = 2.f * s;
        }
        return;
    }
    {
        int f = t >> 2, wd = t & 3;
        unsigned u = 0;
        for (int i = 0; i < 32; i++)
            if (A[(wd*32+i)*(PAST+FUT) + PAST + f]) u |= (1u << i);
        d_maskw[f*4 + wd] = u;
    }
}

// ============ B: padded-bucket scatter — NO hist, NO scan, NO barriers ============
__global__ void kScat(const int* __restrict__ e1, const int* __restrict__ e2) {
    int i = blockIdx.x*256 + threadIdx.x;
    if (i < T1) {
        int s, d;
        if (i < E1N) { s = e1[i]; d = e1[E1N + i]; }
        else         { s = d = i - E1N; }
        int pos = atomicAdd(&d_cur1[d], 1);
        d_csr1[d*PAD + pos] = s;
    } else {
        int j = i - T1;
        if (j >= T2) return;
        int s, d;
        if (j < E2N) { s = e2[j]; d = e2[E2N + j]; }
        else         { s = d = j - E2N; }
        int pos = atomicAdd(&d_cur2[d], 1);
        d_csr2[d*PAD + pos] = s;
    }
}

// ==== C: GAT1 aggregate (blocks < N1) | z2 = M @ x2 (extra blocks) ====
__global__ void kAgg1(const float* __restrict__ bias) {
    __shared__ float sbuf[NO*NO + Z2PB*NO];   // 14 KB union
    int n = blockIdx.x;
    int t = threadIdx.x;

    if (n >= N1) {
        int base = (n - N1) * Z2PB;
        float* Ms  = sbuf;
        float* x2s = sbuf + NO*NO;
        for (int idx = t; idx < NO*NO; idx += 256) Ms[idx] = d_M[idx];
        for (int idx = t; idx < Z2PB*NO; idx += 256) {
            int gl = base*NO + idx;
            x2s[idx] = (gl < N2*NO) ? d_x2[gl] : 0.f;
        }
        __syncthreads();
        for (int idx = t; idx < Z2PB*NO; idx += 256) {
            int ln = idx / NO, c = idx % NO;
            int node = base + ln;
            if (node < N2) {
                float z = 0.f;
                #pragma unroll
                for (int j = 0; j < NO; j++) z += Ms[c*NO + j] * x2s[ln*NO + j];
                d_z2[node*NO + c] = z;
            }
        }
        return;
    }

    int wp = t >> 5;
    int w  = wp >> 1;
    int eh = wp & 1;
    int lane = t & 31;
    int beg = n*PAD;
    int end = beg + d_cur1[n];     // degree count from scatter
    float ad = d_ad1[n*NH + w];

    float* so      = sbuf;          // 50
    float* ssum_sh = sbuf + 64;     // 4
    float* red     = sbuf + 96;     // 256
    if (t < NO) so[t] = 0.f;
    if (t < NH) ssum_sh[t] = 0.f;
    __syncthreads();
    if (t == 0) d_cur1[n] = 0;      // restore for next replay (all threads read above)

    float ssum = 0.f, a0 = 0.f, a1 = 0.f, b0 = 0.f, b1 = 0.f;
    int c0 = lane, c1 = lane + 32;
    bool has1 = (c1 < NO);
    int i = beg + eh;
    for (; i + 2 < end; i += 4) {
        int s0 = d_csr1[i], s1 = d_csr1[i+2];
        float w0 = __expf(lrelu(__ldg(&d_as1[s0*NH + w]) + ad));
        float w1 = __expf(lrelu(__ldg(&d_as1[s1*NH + w]) + ad));
        ssum += w0 + w1;
        const float* h0 = &d_h1[s0*(NH*NO) + w*NO];
        const float* h1 = &d_h1[s1*(NH*NO) + w*NO];
        a0 += w0 * h0[c0];
        b0 += w1 * h1[c0];
        if (has1) { a1 += w0 * h0[c1]; b1 += w1 * h1[c1]; }
    }
    if (i < end) {
        int s0 = d_csr1[i];
        float w0 = __expf(lrelu(__ldg(&d_as1[s0*NH + w]) + ad));
        ssum += w0;
        const float* h0 = &d_h1[s0*(NH*NO) + w*NO];
        a0 += w0 * h0[c0];
        if (has1) a1 += w0 * h0[c1];
    }
    a0 += b0; a1 += b1;
    if (lane == 0) atomicAdd(&ssum_sh[w], ssum);
    __syncthreads();
    float inv = 0.25f / (ssum_sh[w] + 1e-16f);
    atomicAdd(&so[c0], a0 * inv);
    if (has1) atomicAdd(&so[c1], a1 * inv);
    __syncthreads();
    if (t < NO) {
        float v = so[t] + bias[t];
        so[t] = v;
        d_x1o[n*NO + t] = v;
    }
    __syncthreads();
    float p = 0.f;
    for (int r = wp; r < NO; r += 8) {
        float xr = so[r];
        float acc = __ldg(&d_M[r*NO + c0]) * so[c0];
        if (has1) acc += __ldg(&d_M[r*NO + c1]) * so[c1];
        p += acc * xr;
    }
    red[t] = p;
    __syncthreads();
    if (t < 128) red[t] += red[t+128];
    __syncthreads();
    if (t < 64) red[t] += red[t+64];
    __syncthreads();
    if (t < 32) {
        float v = red[t] + red[t+32];
        v = warp_sum(v);
        if (t == 0) d_q1h[n] = -0.5f * v;
    }
}

// ==== D: attention (8 f's/block) -> barrier -> GAT2 aggregate ====
__global__ void __launch_bounds__(256, 4) kD(
        const float* __restrict__ lin,
        const float* __restrict__ asrc, const float* __restrict__ adst,
        const float* __restrict__ bias, float* __restrict__ out) {
    int t = threadIdx.x;
    __shared__ float xt[PAST*51];      // 26112 B
    __shared__ float x2s[8*NO];
    __shared__ float zs[8*NO];
    __shared__ float qh[PAST];
    __shared__ float yv[PAST];
    __shared__ float s_tmp[8];
    __shared__ unsigned msk[8*4];

    {   // ---- attn phase: vb == blockIdx.x, 8 f's ----
        int vb = blockIdx.x;
        int b = vb >> 3, q = vb & 7;
        int fbase = q * 8;

        const float* x1src = d_x1o + (size_t)b*PAST*NO;
        for (int idx = t; idx < PAST*NO; idx += 256) {
            int p = idx / NO, c = idx % NO;
            xt[p*51 + c] = x1src[idx];
        }
        for (int idx = t; idx < 8*NO; idx += 256) {
            int fl = idx / NO, c = idx % NO;
            int nn = (b*FUT + fbase + fl)*NO + c;
            x2s[idx] = d_x2[nn];
            zs[idx]  = d_z2[nn];
        }
        if (t < PAST) { qh[t] = d_q1h[b*PAST + t]; yv[t] = d_y[b*PAST + t]; }
        if (t < 32)   msk[t] = d_maskw[(fbase + (t>>2))*4 + (t&3)];
        __syncthreads();

        int fl = t >> 5;          // warp per f
        int psub = t & 31;
        const float* zrow = zs + fl*NO;
        float sex = 0.f, swv = 0.f;
        #pragma unroll
        for (int k = 0; k < 4; k++) {
            int p = psub + k*32;
            const float* xr = xt + p*51;
            float d0 = 0.f, d1 = 0.f;
            #pragma unroll
            for (int c = 0; c < 25; c++) {
                d0 += zrow[c]      * xr[c];
                d1 += zrow[c + 25] * xr[c + 25];
            }
            float logit = qh[p] + d0 + d1;
            unsigned bit = (msk[fl*4 + k] >> psub) & 1u;
            float ex = bit ? __expf(logit) : 0.f;
            sex += ex;
            swv += ex * yv[p];
        }
        sex = warp_sum(sex);
        swv = warp_sum(swv);
        if (psub == 0) s_tmp[fl] = swv / (sex + 1e-16f);
        __syncthreads();

        if (t < 32) {
            int fl2 = t >> 2, h = t & 3;
            const float* xr = x2s + fl2*NO;
            float acc = 0.f;
            #pragma unroll 10
            for (int k = 0; k < NO; k++) acc += xr[k] * __ldg(&lin[k*NH + h]);
            int n = b*FUT + fbase + fl2;
            float v = acc + s_tmp[fl2] * __ldg(&lin[NO*NH + h]);
            d_h2[n*NH + h]  = v;
            d_as2[n*NH + h] = v * asrc[h];
            d_ad2[n*NH + h] = v * adst[h];
        }
    }
    grid_barrier();
    // ---- agg2 phase: 8 nodes per block, 1:1 ----
    {
        int n = blockIdx.x*8 + (t >> 5);
        int lane = t & 31;
        int beg = n*PAD;
        int cnt = d_cur2[n];
        __syncwarp();
        if (lane == 0) d_cur2[n] = 0;   // restore for next replay
        int end = beg + cnt;
        float4 adv = *(const float4*)&d_ad2[n*NH];
        float ss0=0,ss1=0,ss2=0,ss3=0, ws0=0,ws1=0,ws2=0,ws3=0;
        for (int i = beg + lane; i < end; i += 32) {
            int s = d_csr2[i];
            float4 av = *(const float4*)&d_as2[s*NH];
            float4 hv = *(const float4*)&d_h2[s*NH];
            float e0 = __expf(lrelu(av.x + adv.x));
            float e1 = __expf(lrelu(av.y + adv.y));
            float e2 = __expf(lrelu(av.z + adv.z));
            float e3 = __expf(lrelu(av.w + adv.w));
            ss0+=e0; ws0+=e0*hv.x;
            ss1+=e1; ws1+=e1*hv.y;
            ss2+=e2; ws2+=e2*hv.z;
            ss3+=e3; ws3+=e3*hv.w;
        }
        ss0=warp_sum(ss0); ws0=warp_sum(ws0);
        ss1=warp_sum(ss1); ws1=warp_sum(ws1);
        ss2=warp_sum(ss2); ws2=warp_sum(ws2);
        ss3=warp_sum(ss3); ws3=warp_sum(ws3);
        if (lane == 0) {
            float total = 0.25f*ws0/(ss0+1e-16f) + 0.25f*ws1/(ss1+1e-16f)
                        + 0.25f*ws2/(ss2+1e-16f) + 0.25f*ws3/(ss3+1e-16f);
            out[n] = total + bias[0];
        }
    }
}

// ================= launch: 4 kernels, 3-deep chain, scatter fully parallel =======
extern "C" void kernel_launch(void* const* d_in, const int* in_sizes, int n_in,
                              void* d_out, int out_size) {
    const int*   cat1   = (const int*)  d_in[0];
    const float* num1   = (const float*)d_in[1];
    const int*   cat2   = (const int*)  d_in[2];
    const float* num2   = (const float*)d_in[3];
    const int*   e1     = (const int*)  d_in[4];
    const int*   e2     = (const int*)  d_in[5];
    const int*   A      = (const int*)  d_in[6];
    const float* emb0   = (const float*)d_in[7];
    const float* emb1   = (const float*)d_in[8];
    const float* emb2   = (const float*)d_in[9];
    const float* g1_lin = (const float*)d_in[10];
    const float* g1_as  = (const float*)d_in[11];
    const float* g1_ad  = (const float*)d_in[12];
    const float* g1_b   = (const float*)d_in[13];
    const float* g2_lin = (const float*)d_in[14];
    const float* g2_as  = (const float*)d_in[15];
    const float* g2_ad  = (const float*)d_in[16];
    const float* g2_b   = (const float*)d_in[17];
    const float* W      = (const float*)d_in[18];
    float* out = (float*)d_out;

    static cudaStream_t s1 = nullptr;
    static cudaEvent_t evF = nullptr, evB = nullptr;
    if (!s1) {
        cudaStreamCreateWithFlags(&s1, cudaStreamNonBlocking);
        cudaEventCreateWithFlags(&evF, cudaEventDisableTiming);
        cudaEventCreateWithFlags(&evB, cudaEventDisableTiming);
    }

    cudaEventRecord(evF, 0);
    cudaStreamWaitEvent(s1, evF, 0);

    // side: padded-bucket CSR scatter (single phase, overlaps kA)
    kScat<<<SCB, 256, 0, s1>>>(e1, e2);
    cudaEventRecord(evB, s1);

    // main chain: A -> agg1 -> D
    kA<<<AGRID, 256>>>(cat1, num1, cat2, num2, A, emb0, emb1, emb2,
                       g1_lin, g1_as, g1_ad, W);
    cudaStreamWaitEvent(0, evB, 0);
    kAgg1<<<N1 + Z2B, 256>>>(g1_b);
    kD<<<DGRID, 256>>>(g2_lin, g2_as, g2_ad, g2_b, out);
}